// round 1
// baseline (speedup 1.0000x reference)
#include <cuda_runtime.h>
#include <cstdint>

#define OUTF   11008
#define INF    4096
#define BATCHN 16
#define SPLITK 8
#define KC     (INF / SPLITK)   // 512 k per CTA
#define OTILE  256              // output channels per CTA
#define NTHR   128              // 2 output channels per thread
#define XROW   20               // padded row stride (floats) for x_t[k][b]; 80B, 16B-aligned

// Split-K partial sums: [SPLITK][BATCHN][OUTF]  (5.6 MB device-global scratch)
__device__ float g_partial[SPLITK * BATCHN * OUTF];

__device__ __forceinline__ unsigned long long dup_f2(float f) {
    unsigned long long r;
    asm("mov.b64 %0, {%1, %1};" : "=l"(r) : "f"(f));
    return r;
}
__device__ __forceinline__ void fma_f32x2(unsigned long long& d,
                                          unsigned long long a,
                                          unsigned long long b) {
    asm("fma.rn.f32x2 %0, %1, %2, %0;" : "+l"(d) : "l"(a), "l"(b));
}
__device__ __forceinline__ float2 unpack_f2(unsigned long long v) {
    float2 r;
    asm("mov.b64 {%0, %1}, %2;" : "=f"(r.x), "=f"(r.y) : "l"(v));
    return r;
}

__global__ __launch_bounds__(NTHR) void qlinear_main(
    const float* __restrict__ x,
    const int*   __restrict__ w,
    const float* __restrict__ scale)
{
    __shared__ float xs[KC * XROW];   // x transposed: xs[k*XROW + b]

    const int tid   = threadIdx.x;
    const int obase = blockIdx.x * OTILE;
    const int kbase = blockIdx.y * KC;

    // ---- stage x chunk transposed into smem (coalesced gmem reads) ----
    #pragma unroll
    for (int i = 0; i < (BATCHN * KC) / NTHR; ++i) {   // 64 elems/thread
        int e = tid + i * NTHR;
        int b = e >> 9;          // / KC (512)
        int k = e & (KC - 1);
        xs[k * XROW + b] = x[b * INF + kbase + k];
    }
    __syncthreads();

    const int o0 = obase + 2 * tid;
    const int o1 = o0 + 1;
    const int4* p0 = (const int4*)(w + (size_t)o0 * INF + kbase);
    const int4* p1 = (const int4*)(w + (size_t)o1 * INF + kbase);

    // accumulators: 8 f32x2 pairs (16 batch) per output channel
    unsigned long long acc0[8], acc1[8];
    #pragma unroll
    for (int i = 0; i < 8; ++i) { acc0[i] = 0ULL; acc1[i] = 0ULL; }

    // software-pipelined weight loads: 32B (full sector) per o per 8-k step
    int4 a00 = __ldcs(p0 + 0), a01 = __ldcs(p0 + 1);
    int4 a10 = __ldcs(p1 + 0), a11 = __ldcs(p1 + 1);

    const int NIT = KC / 8;   // 64
    for (int it = 0; it < NIT; ++it) {
        int nx = (it + 1 < NIT) ? (it + 1) : it;   // clamp: safe redundant load
        int4 n00 = __ldcs(p0 + 2 * nx);
        int4 n01 = __ldcs(p0 + 2 * nx + 1);
        int4 n10 = __ldcs(p1 + 2 * nx);
        int4 n11 = __ldcs(p1 + 2 * nx + 1);

        const int w0[8] = {a00.x, a00.y, a00.z, a00.w, a01.x, a01.y, a01.z, a01.w};
        const int w1[8] = {a10.x, a10.y, a10.z, a10.w, a11.x, a11.y, a11.z, a11.w};
        const int kb = it * 8;

        #pragma unroll
        for (int j = 0; j < 8; ++j) {
            unsigned long long d0 = dup_f2((float)w0[j]);
            unsigned long long d1 = dup_f2((float)w1[j]);
            // all 32 lanes read the SAME row -> LDS.128 broadcast (N=1)
            const ulonglong2* xr = (const ulonglong2*)(xs + (kb + j) * XROW);
            ulonglong2 xa = xr[0];   // b 0..3
            ulonglong2 xb = xr[1];   // b 4..7
            ulonglong2 xc = xr[2];   // b 8..11
            ulonglong2 xd = xr[3];   // b 12..15
            fma_f32x2(acc0[0], d0, xa.x);  fma_f32x2(acc1[0], d1, xa.x);
            fma_f32x2(acc0[1], d0, xa.y);  fma_f32x2(acc1[1], d1, xa.y);
            fma_f32x2(acc0[2], d0, xb.x);  fma_f32x2(acc1[2], d1, xb.x);
            fma_f32x2(acc0[3], d0, xb.y);  fma_f32x2(acc1[3], d1, xb.y);
            fma_f32x2(acc0[4], d0, xc.x);  fma_f32x2(acc1[4], d1, xc.x);
            fma_f32x2(acc0[5], d0, xc.y);  fma_f32x2(acc1[5], d1, xc.y);
            fma_f32x2(acc0[6], d0, xd.x);  fma_f32x2(acc1[6], d1, xd.x);
            fma_f32x2(acc0[7], d0, xd.y);  fma_f32x2(acc1[7], d1, xd.y);
        }
        a00 = n00; a01 = n01; a10 = n10; a11 = n11;
    }

    // ---- epilogue: scale and write partials (plain stores, deterministic) ----
    const float s0 = scale[o0];
    const float s1 = scale[o1];
    float* pp = g_partial + (size_t)blockIdx.y * BATCHN * OUTF;

    #pragma unroll
    for (int p = 0; p < 8; ++p) {
        float2 v0 = unpack_f2(acc0[p]);   // (b=2p, b=2p+1) for o0
        float2 v1 = unpack_f2(acc1[p]);   // (b=2p, b=2p+1) for o1
        float2 r0 = make_float2(v0.x * s0, v1.x * s1);   // batch 2p,   (o0,o1)
        float2 r1 = make_float2(v0.y * s0, v1.y * s1);   // batch 2p+1, (o0,o1)
        *(float2*)(pp + (size_t)(2 * p)     * OUTF + o0) = r0;
        *(float2*)(pp + (size_t)(2 * p + 1) * OUTF + o0) = r1;
    }
}

__global__ void qlinear_reduce(const float* __restrict__ bias,
                               float* __restrict__ out)
{
    int i = blockIdx.x * blockDim.x + threadIdx.x;   // over BATCHN*OUTF
    if (i >= BATCHN * OUTF) return;
    int o = i % OUTF;
    float s = bias[o];
    #pragma unroll
    for (int ky = 0; ky < SPLITK; ++ky)
        s += g_partial[(size_t)ky * BATCHN * OUTF + i];
    out[i] = s;
}

extern "C" void kernel_launch(void* const* d_in, const int* in_sizes, int n_in,
                              void* d_out, int out_size)
{
    const float* x     = (const float*)d_in[0];
    const int*   w     = (const int*)  d_in[1];
    const float* scale = (const float*)d_in[2];
    const float* bias  = (const float*)d_in[3];
    float* out = (float*)d_out;

    dim3 grid(OUTF / OTILE, SPLITK);   // (43, 8) = 344 CTAs
    qlinear_main<<<grid, NTHR>>>(x, w, scale);

    int total = BATCHN * OUTF;
    qlinear_reduce<<<(total + 255) / 256, 256>>>(bias, out);
}

// round 3
// speedup vs baseline: 1.9102x; 1.9102x over previous
#include <cuda_runtime.h>
#include <cstdint>

#define OUTF   11008
#define INF    4096
#define BATCHN 16
#define SPLITK 32
#define KC     (INF / SPLITK)        // 128 k per CTA
#define KTILE  32                    // k per pipeline stage
#define NSTAGE (KC / KTILE)          // 4 stages
#define OTILE  256                   // output rows per CTA
#define NTHR   128                   // 2 rows per thread
#define WROW   36                    // padded ints per smem W row (144B, 16B-aligned, bank-rotated)
#define WBUF   (OTILE * WROW)        // ints per W buffer (9216)
#define XROW   20                    // padded floats per xs row (80B)
#define SMEM_BYTES (2 * WBUF * 4 + KC * XROW * 4)   // 73728 + 10240 = 83968 B

// Split-K partials: [SPLITK][BATCHN][OUTF] = 22.5 MB device-global scratch
__device__ float g_partial[SPLITK * BATCHN * OUTF];

__device__ __forceinline__ unsigned long long dup_f2(float f) {
    unsigned long long r;
    asm("mov.b64 %0, {%1, %1};" : "=l"(r) : "f"(f));
    return r;
}
__device__ __forceinline__ void fma_f32x2(unsigned long long& d,
                                          unsigned long long a,
                                          unsigned long long b) {
    asm("fma.rn.f32x2 %0, %1, %2, %0;" : "+l"(d) : "l"(a), "l"(b));
}
__device__ __forceinline__ float2 unpack_f2(unsigned long long v) {
    float2 r;
    asm("mov.b64 {%0, %1}, %2;" : "=f"(r.x), "=f"(r.y) : "l"(v));
    return r;
}
__device__ __forceinline__ void cp_async16(unsigned smem_addr, const void* gptr) {
    asm volatile("cp.async.cg.shared.global [%0], [%1], 16;\n"
                 :: "r"(smem_addr), "l"(gptr));
}
__device__ __forceinline__ void cp_commit() {
    asm volatile("cp.async.commit_group;\n" ::: "memory");
}
__device__ __forceinline__ void cp_wait1() {
    asm volatile("cp.async.wait_group 1;\n" ::: "memory");
}

__global__ __launch_bounds__(NTHR) void qlinear_main(
    const float* __restrict__ x,
    const int*   __restrict__ w,
    const float* __restrict__ scale)
{
    extern __shared__ int sm[];
    int*   ws = sm;                          // 2 x WBUF ints
    float* xs = (float*)(sm + 2 * WBUF);     // KC x XROW floats

    const int tid   = threadIdx.x;
    const int obase = blockIdx.x * OTILE;
    const int kbase = blockIdx.y * KC;

    // ---- coalesced W stage issue: warp = 4 rows x 8 chunks of 16B (nL=4/op) ----
    const int row0  = tid >> 3;              // 0..15
    const int chunk = tid & 7;               // 0..7
    const int* gsrc_base = w + (size_t)(obase + row0) * INF + kbase + chunk * 4;
    const unsigned sdst_base =
        (unsigned)__cvta_generic_to_shared(ws + row0 * WROW + chunk * 4);

    // issue stage 0 into buffer 0
    {
        const int* g = gsrc_base;            // + 0*KTILE
        #pragma unroll
        for (int i = 0; i < 16; ++i)
            cp_async16(sdst_base + (unsigned)(i * 16 * WROW * 4),
                       g + (size_t)i * 16 * INF);
        cp_commit();
    }

    // ---- stage x chunk transposed into smem (overlaps with cp.async stage 0) ----
    #pragma unroll
    for (int i = 0; i < (BATCHN * KC) / NTHR; ++i) {   // 16 elems/thread
        int e = tid + i * NTHR;
        int b = e >> 7;                  // / KC(128)
        int k = e & (KC - 1);
        xs[k * XROW + b] = x[b * INF + kbase + k];
    }

    const int o0 = obase + 2 * tid;
    const int o1 = o0 + 1;

    unsigned long long acc0[8], acc1[8];
    #pragma unroll
    for (int i = 0; i < 8; ++i) { acc0[i] = 0ULL; acc1[i] = 0ULL; }

    #pragma unroll 1
    for (int s = 0; s < NSTAGE; ++s) {
        // issue stage s+1 into the other buffer (or empty commit on last stage)
        if (s + 1 < NSTAGE) {
            const int bi = (s + 1) & 1;
            const int* g = gsrc_base + (s + 1) * KTILE;
            const unsigned sd = sdst_base + (unsigned)(bi * WBUF * 4);
            #pragma unroll
            for (int i = 0; i < 16; ++i)
                cp_async16(sd + (unsigned)(i * 16 * WROW * 4),
                           g + (size_t)i * 16 * INF);
        }
        cp_commit();
        cp_wait1();            // stage s complete (<=1 group still in flight)
        __syncthreads();

        const int* wrow = ws + (s & 1) * WBUF + (2 * tid) * WROW;

        #pragma unroll
        for (int j8 = 0; j8 < KTILE / 8; ++j8) {
            int4 a00 = *(const int4*)(wrow + j8 * 8);
            int4 a01 = *(const int4*)(wrow + j8 * 8 + 4);
            int4 a10 = *(const int4*)(wrow + WROW + j8 * 8);
            int4 a11 = *(const int4*)(wrow + WROW + j8 * 8 + 4);

            const int w0[8] = {a00.x, a00.y, a00.z, a00.w, a01.x, a01.y, a01.z, a01.w};
            const int w1[8] = {a10.x, a10.y, a10.z, a10.w, a11.x, a11.y, a11.z, a11.w};
            const int kb = s * KTILE + j8 * 8;

            #pragma unroll
            for (int j = 0; j < 8; ++j) {
                unsigned long long d0 = dup_f2((float)w0[j]);
                unsigned long long d1 = dup_f2((float)w1[j]);
                const ulonglong2* xr = (const ulonglong2*)(xs + (kb + j) * XROW);
                ulonglong2 xa = xr[0];
                ulonglong2 xb = xr[1];
                ulonglong2 xc = xr[2];
                ulonglong2 xd = xr[3];
                fma_f32x2(acc0[0], d0, xa.x);  fma_f32x2(acc1[0], d1, xa.x);
                fma_f32x2(acc0[1], d0, xa.y);  fma_f32x2(acc1[1], d1, xa.y);
                fma_f32x2(acc0[2], d0, xb.x);  fma_f32x2(acc1[2], d1, xb.x);
                fma_f32x2(acc0[3], d0, xb.y);  fma_f32x2(acc1[3], d1, xb.y);
                fma_f32x2(acc0[4], d0, xc.x);  fma_f32x2(acc1[4], d1, xc.x);
                fma_f32x2(acc0[5], d0, xc.y);  fma_f32x2(acc1[5], d1, xc.y);
                fma_f32x2(acc0[6], d0, xd.x);  fma_f32x2(acc1[6], d1, xd.x);
                fma_f32x2(acc0[7], d0, xd.y);  fma_f32x2(acc1[7], d1, xd.y);
            }
        }
        __syncthreads();       // protect buffer reuse before next issue
    }

    // ---- epilogue: scale and write split-K partials ----
    const float s0 = scale[o0];
    const float s1 = scale[o1];
    float* pp = g_partial + (size_t)blockIdx.y * BATCHN * OUTF;

    #pragma unroll
    for (int p = 0; p < 8; ++p) {
        float2 v0 = unpack_f2(acc0[p]);
        float2 v1 = unpack_f2(acc1[p]);
        float2 r0 = make_float2(v0.x * s0, v1.x * s1);
        float2 r1 = make_float2(v0.y * s0, v1.y * s1);
        *(float2*)(pp + (size_t)(2 * p)     * OUTF + o0) = r0;
        *(float2*)(pp + (size_t)(2 * p + 1) * OUTF + o0) = r1;
    }
}

__global__ void qlinear_reduce(const float* __restrict__ bias,
                               float* __restrict__ out)
{
    const int n4 = BATCHN * OUTF / 4;
    int i = blockIdx.x * blockDim.x + threadIdx.x;
    if (i >= n4) return;
    int o4 = i % (OUTF / 4);
    float4 s = ((const float4*)bias)[o4];
    const float4* gp = (const float4*)g_partial;
    #pragma unroll 8
    for (int ky = 0; ky < SPLITK; ++ky) {
        float4 p = gp[(size_t)ky * n4 + i];
        s.x += p.x; s.y += p.y; s.z += p.z; s.w += p.w;
    }
    ((float4*)out)[i] = s;
}

extern "C" void kernel_launch(void* const* d_in, const int* in_sizes, int n_in,
                              void* d_out, int out_size)
{
    const float* x     = (const float*)d_in[0];
    const int*   w     = (const int*)  d_in[1];
    const float* scale = (const float*)d_in[2];
    const float* bias  = (const float*)d_in[3];
    float* out = (float*)d_out;

    cudaFuncSetAttribute(qlinear_main,
                         cudaFuncAttributeMaxDynamicSharedMemorySize, SMEM_BYTES);

    dim3 grid(OUTF / OTILE, SPLITK);   // (43, 32) = 1376 CTAs
    qlinear_main<<<grid, NTHR, SMEM_BYTES>>>(x, w, scale);

    int total4 = BATCHN * OUTF / 4;
    qlinear_reduce<<<(total4 + 255) / 256, 256>>>(bias, out);
}